// round 13
// baseline (speedup 1.0000x reference)
#include <cuda_runtime.h>
#include <math.h>

#define SEQ  32768
#define HID  1024
#define RPB  8                  // rows per block (one per warp)
#define NB   (SEQ / RPB)        // 4096 matvec blocks

// Scratch (no device allocation allowed). Both arrays are fully rewritten
// by matvec_kernel on every call -> no init, no reset, deterministic.
__device__ float  g_energies[SEQ];
__device__ double g_partial[NB];

// ---------------------------------------------------------------------------
// Kernel 1: energies[row] = dot(enc[row,:], hidden)
// One warp per row; block writes sum(exp(energy)) over its 8 rows (double)
// to g_partial[blockIdx] — plain store, no atomics, no ordering ambiguity.
// ---------------------------------------------------------------------------
__global__ __launch_bounds__(256) void matvec_kernel(
    const float* __restrict__ hidden,
    const float* __restrict__ enc)
{
    __shared__ float4 sh_h[HID / 4];  // 4 KB
    __shared__ float  sh_e[RPB];

    int tid = threadIdx.x;
    sh_h[tid] = reinterpret_cast<const float4*>(hidden)[tid];
    __syncthreads();

    int warp = tid >> 5;
    int lane = tid & 31;
    int row  = blockIdx.x * RPB + warp;

    const float4* e4 = reinterpret_cast<const float4*>(enc)
                     + (size_t)row * (HID / 4);

    float acc = 0.0f;
#pragma unroll
    for (int i = 0; i < 8; i++) {
        float4 a = __ldcs(e4 + i * 32 + lane);   // streaming: read-once data
        float4 h = sh_h[i * 32 + lane];
        acc = fmaf(a.x, h.x, acc);
        acc = fmaf(a.y, h.y, acc);
        acc = fmaf(a.z, h.z, acc);
        acc = fmaf(a.w, h.w, acc);
    }

#pragma unroll
    for (int o = 16; o; o >>= 1)
        acc += __shfl_xor_sync(0xffffffffu, acc, o);

    if (lane == 0) {
        g_energies[row] = acc;
        sh_e[warp] = acc;
    }
    __syncthreads();

    // warp 0, lanes 0..7: fixed-order reduce of 8 double exps -> one store
    if (tid < RPB) {
        double v = exp((double)sh_e[tid]);
#pragma unroll
        for (int o = RPB / 2; o; o >>= 1)
            v += __shfl_xor_sync(0xffu, v, o);
        if (tid == 0)
            g_partial[blockIdx.x] = v;
    }
}

// ---------------------------------------------------------------------------
// Kernel 2: every block redundantly sums the 4096 partials (L2-hot, fixed
// order -> deterministic), then writes out[i] = exp(e[i]) / S.
// ---------------------------------------------------------------------------
__global__ __launch_bounds__(512) void normalize_kernel(float* __restrict__ out)
{
    __shared__ double red[16];

    int tid  = threadIdx.x;
    int lane = tid & 31;
    int warp = tid >> 5;

    // fixed-order per-thread partial: 8 strided doubles each
    double s = 0.0;
#pragma unroll
    for (int i = 0; i < NB / 512; i++)
        s += g_partial[i * 512 + tid];

#pragma unroll
    for (int o = 16; o; o >>= 1)
        s += __shfl_xor_sync(0xffffffffu, s, o);
    if (lane == 0) red[warp] = s;
    __syncthreads();
    if (warp == 0) {
        double v = (lane < 16) ? red[lane] : 0.0;
#pragma unroll
        for (int o = 8; o; o >>= 1)
            v += __shfl_xor_sync(0xffffffffu, v, o);
        if (lane == 0) red[0] = v;
    }
    __syncthreads();
    double inv = 1.0 / red[0];

    int i = blockIdx.x * 512 + tid;
    out[i] = (float)(exp((double)g_energies[i]) * inv);
}

// ---------------------------------------------------------------------------
extern "C" void kernel_launch(void* const* d_in, const int* in_sizes, int n_in,
                              void* d_out, int out_size)
{
    const float* hidden = (const float*)d_in[0];   // [1024]
    const float* enc    = (const float*)d_in[1];   // [32768, 1024]
    float* out          = (float*)d_out;           // [1,1,32768]

    matvec_kernel<<<NB, 256>>>(hidden, enc);
    normalize_kernel<<<SEQ / 512, 512>>>(out);
}

// round 14
// speedup vs baseline: 1.2126x; 1.2126x over previous
#include <cuda_runtime.h>
#include <math.h>

#define SEQ  32768
#define HID  1024
#define RPB  8                  // rows per block (one per warp)
#define NB   (SEQ / RPB)        // 4096 matvec blocks

// Scratch (no device allocation allowed). All arrays fully rewritten by
// matvec_kernel every call -> no init, no reset, deterministic.
__device__ float g_energies[SEQ];
__device__ float g_bm[NB];      // per-block max
__device__ float g_bs[NB];      // per-block sum(exp(e - max))

// ---------------------------------------------------------------------------
// Kernel 1: energies[row] = dot(enc[row,:], hidden); block writes its
// log-sum-exp pair (m_b, s_b) over its 8 rows. All float, no atomics.
// ---------------------------------------------------------------------------
__global__ __launch_bounds__(256) void matvec_kernel(
    const float* __restrict__ hidden,
    const float* __restrict__ enc)
{
    __shared__ float4 sh_h[HID / 4];  // 4 KB
    __shared__ float  sh_e[RPB];

    int tid = threadIdx.x;
    sh_h[tid] = reinterpret_cast<const float4*>(hidden)[tid];
    __syncthreads();

    int warp = tid >> 5;
    int lane = tid & 31;
    int row  = blockIdx.x * RPB + warp;

    const float4* e4 = reinterpret_cast<const float4*>(enc)
                     + (size_t)row * (HID / 4);

    float acc = 0.0f;
#pragma unroll
    for (int i = 0; i < 8; i++) {
        float4 a = __ldcs(e4 + i * 32 + lane);   // streaming: read-once data
        float4 h = sh_h[i * 32 + lane];
        acc = fmaf(a.x, h.x, acc);
        acc = fmaf(a.y, h.y, acc);
        acc = fmaf(a.z, h.z, acc);
        acc = fmaf(a.w, h.w, acc);
    }

#pragma unroll
    for (int o = 16; o; o >>= 1)
        acc += __shfl_xor_sync(0xffffffffu, acc, o);

    if (lane == 0) {
        g_energies[row] = acc;
        sh_e[warp] = acc;
    }
    __syncthreads();

    // lanes 0..7 of warp 0: 8-lane max + exp-sum, fixed order, all float
    if (tid < RPB) {
        float e = sh_e[tid];
        float m = e;
#pragma unroll
        for (int o = RPB / 2; o; o >>= 1)
            m = fmaxf(m, __shfl_xor_sync(0xffu, m, o));
        float p = __expf(e - m);
#pragma unroll
        for (int o = RPB / 2; o; o >>= 1)
            p += __shfl_xor_sync(0xffu, p, o);
        if (tid == 0) {
            g_bm[blockIdx.x] = m;
            g_bs[blockIdx.x] = p;
        }
    }
}

// ---------------------------------------------------------------------------
// Kernel 2: each block redundantly combines the 4096 (m,s) pairs (registers,
// L2-hot, fixed order -> deterministic), then one output element per thread.
// ---------------------------------------------------------------------------
__global__ __launch_bounds__(512) void normalize_kernel(float* __restrict__ out)
{
    __shared__ float redm[16], reds[16];

    int tid  = threadIdx.x;
    int lane = tid & 31;
    int warp = tid >> 5;

    // hold this thread's 8 pairs in registers
    float bm[NB / 512], bs[NB / 512];
#pragma unroll
    for (int i = 0; i < NB / 512; i++) {
        bm[i] = g_bm[i * 512 + tid];
        bs[i] = g_bs[i * 512 + tid];
    }

    // global max M
    float m = bm[0];
#pragma unroll
    for (int i = 1; i < NB / 512; i++) m = fmaxf(m, bm[i]);
#pragma unroll
    for (int o = 16; o; o >>= 1)
        m = fmaxf(m, __shfl_xor_sync(0xffffffffu, m, o));
    if (lane == 0) redm[warp] = m;
    __syncthreads();
    if (warp == 0) {
        float v = (lane < 16) ? redm[lane] : -INFINITY;
#pragma unroll
        for (int o = 8; o; o >>= 1)
            v = fmaxf(v, __shfl_xor_sync(0xffffffffu, v, o));
        if (lane == 0) redm[0] = v;
    }
    __syncthreads();
    const float M = redm[0];

    // global sum S = sum_b s_b * exp(m_b - M)
    float s = 0.0f;
#pragma unroll
    for (int i = 0; i < NB / 512; i++)
        s += bs[i] * __expf(bm[i] - M);
#pragma unroll
    for (int o = 16; o; o >>= 1)
        s += __shfl_xor_sync(0xffffffffu, s, o);
    if (lane == 0) reds[warp] = s;
    __syncthreads();
    if (warp == 0) {
        float v = (lane < 16) ? reds[lane] : 0.0f;
#pragma unroll
        for (int o = 8; o; o >>= 1)
            v += __shfl_xor_sync(0xffffffffu, v, o);
        if (lane == 0) reds[0] = v;
    }
    __syncthreads();
    const float inv = 1.0f / reds[0];

    int i = blockIdx.x * 512 + tid;
    out[i] = __expf(g_energies[i] - M) * inv;
}

// ---------------------------------------------------------------------------
extern "C" void kernel_launch(void* const* d_in, const int* in_sizes, int n_in,
                              void* d_out, int out_size)
{
    const float* hidden = (const float*)d_in[0];   // [1024]
    const float* enc    = (const float*)d_in[1];   // [32768, 1024]
    float* out          = (float*)d_out;           // [1,1,32768]

    matvec_kernel<<<NB, 256>>>(hidden, enc);
    normalize_kernel<<<SEQ / 512, 512>>>(out);
}

// round 15
// speedup vs baseline: 1.2255x; 1.0106x over previous
#include <cuda_runtime.h>
#include <math.h>

#define SEQ  32768
#define HID  1024
#define RPB  8                  // rows per block (one per warp)
#define NB   (SEQ / RPB)        // 4096 matvec blocks

// Scratch (no device allocation allowed). All arrays fully rewritten by
// matvec_kernel every call -> no init, no reset, deterministic.
__device__ float g_energies[SEQ];
__device__ float g_bm[NB];      // per-block max
__device__ float g_bs[NB];      // per-block sum(exp(e - max))

// ---------------------------------------------------------------------------
// Kernel 1: energies[row] = dot(enc[row,:], hidden); block writes its
// log-sum-exp pair (m_b, s_b) over its 8 rows. All float, no atomics.
// ---------------------------------------------------------------------------
__global__ __launch_bounds__(256) void matvec_kernel(
    const float* __restrict__ hidden,
    const float* __restrict__ enc)
{
    __shared__ float4 sh_h[HID / 4];  // 4 KB
    __shared__ float  sh_e[RPB];

    int tid = threadIdx.x;
    sh_h[tid] = reinterpret_cast<const float4*>(hidden)[tid];
    __syncthreads();

    int warp = tid >> 5;
    int lane = tid & 31;
    int row  = blockIdx.x * RPB + warp;

    const float4* e4 = reinterpret_cast<const float4*>(enc)
                     + (size_t)row * (HID / 4);

    float acc = 0.0f;
#pragma unroll
    for (int i = 0; i < 8; i++) {
        float4 a = __ldcs(e4 + i * 32 + lane);   // streaming: read-once data
        float4 h = sh_h[i * 32 + lane];
        acc = fmaf(a.x, h.x, acc);
        acc = fmaf(a.y, h.y, acc);
        acc = fmaf(a.z, h.z, acc);
        acc = fmaf(a.w, h.w, acc);
    }

#pragma unroll
    for (int o = 16; o; o >>= 1)
        acc += __shfl_xor_sync(0xffffffffu, acc, o);

    if (lane == 0) {
        g_energies[row] = acc;
        sh_e[warp] = acc;
    }
    __syncthreads();

    // lanes 0..7 of warp 0: 8-lane max + exp-sum, fixed order, all float
    if (tid < RPB) {
        float e = sh_e[tid];
        float m = e;
#pragma unroll
        for (int o = RPB / 2; o; o >>= 1)
            m = fmaxf(m, __shfl_xor_sync(0xffu, m, o));
        float p = __expf(e - m);
#pragma unroll
        for (int o = RPB / 2; o; o >>= 1)
            p += __shfl_xor_sync(0xffu, p, o);
        if (tid == 0) {
            g_bm[blockIdx.x] = m;
            g_bs[blockIdx.x] = p;
        }
    }

    // PDL: signal this block's writes are done so the dependent normalize
    // kernel (already resident, spinning in GridDependencySynchronize) can
    // proceed as soon as ALL matvec blocks have triggered.
    cudaTriggerProgrammaticLaunchCompletion();
}

// ---------------------------------------------------------------------------
// Kernel 2 (PDL secondary): launched programmatically during kernel 1;
// waits for kernel 1's completion, then combines the 4096 (m,s) pairs
// (L2-hot, fixed order -> deterministic) and writes one output per thread.
// ---------------------------------------------------------------------------
__global__ __launch_bounds__(512) void normalize_kernel(float* __restrict__ out)
{
    __shared__ float redm[16], reds[16];

    int tid  = threadIdx.x;
    int lane = tid & 31;
    int warp = tid >> 5;

    // Wait until matvec's writes (g_energies, g_bm, g_bs) are visible.
    cudaGridDependencySynchronize();

    // hold this thread's 8 pairs in registers
    float bm[NB / 512], bs[NB / 512];
#pragma unroll
    for (int i = 0; i < NB / 512; i++) {
        bm[i] = g_bm[i * 512 + tid];
        bs[i] = g_bs[i * 512 + tid];
    }

    // global max M
    float m = bm[0];
#pragma unroll
    for (int i = 1; i < NB / 512; i++) m = fmaxf(m, bm[i]);
#pragma unroll
    for (int o = 16; o; o >>= 1)
        m = fmaxf(m, __shfl_xor_sync(0xffffffffu, m, o));
    if (lane == 0) redm[warp] = m;
    __syncthreads();
    if (warp == 0) {
        float v = (lane < 16) ? redm[lane] : -INFINITY;
#pragma unroll
        for (int o = 8; o; o >>= 1)
            v = fmaxf(v, __shfl_xor_sync(0xffffffffu, v, o));
        if (lane == 0) redm[0] = v;
    }
    __syncthreads();
    const float M = redm[0];

    // global sum S = sum_b s_b * exp(m_b - M)
    float s = 0.0f;
#pragma unroll
    for (int i = 0; i < NB / 512; i++)
        s += bs[i] * __expf(bm[i] - M);
#pragma unroll
    for (int o = 16; o; o >>= 1)
        s += __shfl_xor_sync(0xffffffffu, s, o);
    if (lane == 0) reds[warp] = s;
    __syncthreads();
    if (warp == 0) {
        float v = (lane < 16) ? reds[lane] : 0.0f;
#pragma unroll
        for (int o = 8; o; o >>= 1)
            v += __shfl_xor_sync(0xffffffffu, v, o);
        if (lane == 0) reds[0] = v;
    }
    __syncthreads();
    const float inv = 1.0f / reds[0];

    int i = blockIdx.x * 512 + tid;
    out[i] = __expf(g_energies[i] - M) * inv;
}

// ---------------------------------------------------------------------------
extern "C" void kernel_launch(void* const* d_in, const int* in_sizes, int n_in,
                              void* d_out, int out_size)
{
    const float* hidden = (const float*)d_in[0];   // [1024]
    const float* enc    = (const float*)d_in[1];   // [32768, 1024]
    float* out          = (float*)d_out;           // [1,1,32768]

    matvec_kernel<<<NB, 256>>>(hidden, enc);

    // Launch normalize with Programmatic Dependent Launch: it becomes
    // resident while matvec runs and self-synchronizes on matvec's writes,
    // hiding the ~4us inter-kernel launch gap.
    cudaLaunchConfig_t cfg = {};
    cfg.gridDim  = dim3(SEQ / 512);
    cfg.blockDim = dim3(512);
    cudaLaunchAttribute attrs[1];
    attrs[0].id = cudaLaunchAttributeProgrammaticStreamSerialization;
    attrs[0].val.programmaticStreamSerializationAllowed = 1;
    cfg.attrs    = attrs;
    cfg.numAttrs = 1;
    cudaError_t e = cudaLaunchKernelEx(&cfg, normalize_kernel, out);
    if (e != cudaSuccess) {
        // Fallback: plain serialized launch (still correct).
        normalize_kernel<<<SEQ / 512, 512>>>(out);
    }
}